// round 11
// baseline (speedup 1.0000x reference)
#include <cuda_runtime.h>
#include <cuda_bf16.h>
#include <cstdint>

#define NROWS 8192
#define DDIM  256
#define BM    128
#define BN    128
#define NBLK  64                      // 64 row blocks of 128
#define THREADS 512
#define NOFFD 2016                    // strict upper-triangle tiles
#define GCH   8                       // gather chunks (8 x 8 >= 63)

#define SA_BYTES (BM*512)             // 65536
#define SB_BYTES (BN*512)             // 65536 per buffer
#define SCOL_OFF (SA_BYTES + 2*SB_BYTES)         // 196608
#define SMEM_BYTES (SCOL_OFF + 3*4*128*4)        // +6144 = 202752

__device__ __align__(16) __nv_bfloat16 g_fn[NROWS*DDIM];
__device__ unsigned char g_lab8[NROWS];
__device__ float g_row[3][16][NROWS];            // [stat][slot y*4+wn][row]
__device__ float g_colS[NOFFD*128];
__device__ float g_colP[NOFFD*128];
__device__ float g_colC[NOFFD*128];
__device__ float g_gat[3][GCH][NROWS];           // parallel gather partials
__device__ float g_red[64][2];
__device__ unsigned int g_ctr;

// ---------------- PTX helpers -------------------------------------------------
__device__ __forceinline__ uint32_t smem_u32(const void* p) {
    uint32_t a;
    asm("{ .reg .u64 t; cvta.to.shared.u64 t, %1; cvt.u32.u64 %0, t; }" : "=r"(a) : "l"(p));
    return a;
}
__device__ __forceinline__ float ex2f(float x) {
    float r; asm("ex2.approx.f32 %0, %1;" : "=f"(r) : "f"(x)); return r;
}
__device__ __forceinline__ void cpasync16(uint32_t dst, const void* src) {
    asm volatile("cp.async.cg.shared.global [%0], [%1], 16;" :: "r"(dst), "l"(src));
}
#define CP_COMMIT() asm volatile("cp.async.commit_group;" ::: "memory")
#define CP_WAIT0()  asm volatile("cp.async.wait_group 0;" ::: "memory")

__device__ __forceinline__ void ldsm_x4(uint32_t& r0, uint32_t& r1, uint32_t& r2,
                                        uint32_t& r3, uint32_t addr) {
    asm volatile("ldmatrix.sync.aligned.m8n8.x4.shared.b16 {%0,%1,%2,%3}, [%4];\n"
                 : "=r"(r0), "=r"(r1), "=r"(r2), "=r"(r3) : "r"(addr));
}
__device__ __forceinline__ void mma16816(float& d0, float& d1, float& d2, float& d3,
                                         uint32_t a0, uint32_t a1, uint32_t a2,
                                         uint32_t a3, uint32_t b0, uint32_t b1) {
    asm volatile("mma.sync.aligned.m16n8k16.row.col.f32.bf16.bf16.f32 "
                 "{%0,%1,%2,%3}, {%4,%5,%6,%7}, {%8,%9}, {%0,%1,%2,%3};\n"
                 : "+f"(d0), "+f"(d1), "+f"(d2), "+f"(d3)
                 : "r"(a0), "r"(a1), "r"(a2), "r"(a3), "r"(b0), "r"(b1));
}

// ---------------- Phase 0: zero row-partial buffers ---------------------------
__global__ void zero_kernel() {
    int i = blockIdx.x*blockDim.x + threadIdx.x;
    ((float4*)&g_row[0][0][0])[i] = make_float4(0.f, 0.f, 0.f, 0.f);
}

// ---------------- Phase 1: normalize rows -> bf16, labels -> bytes ------------
__global__ void prep_kernel(const float* __restrict__ feat,
                            const long long* __restrict__ lab) {
    int row  = (blockIdx.x * blockDim.x + threadIdx.x) >> 5;
    int lane = threadIdx.x & 31;
    if (row >= NROWS) return;
    const float4* fp = (const float4*)(feat + (size_t)row*DDIM);
    float4 x0 = fp[lane], x1 = fp[lane + 32];
    float ss = x0.x*x0.x + x0.y*x0.y + x0.z*x0.z + x0.w*x0.w
             + x1.x*x1.x + x1.y*x1.y + x1.z*x1.z + x1.w*x1.w;
#pragma unroll
    for (int o = 16; o > 0; o >>= 1) ss += __shfl_xor_sync(0xffffffffu, ss, o);
    float sc = 1.f / fmaxf(sqrtf(ss), 1e-6f);
    __nv_bfloat162* bp = (__nv_bfloat162*)(g_fn + (size_t)row*DDIM);
    bp[lane*2+0]    = __floats2bfloat162_rn(x0.x*sc, x0.y*sc);
    bp[lane*2+1]    = __floats2bfloat162_rn(x0.z*sc, x0.w*sc);
    bp[64+lane*2+0] = __floats2bfloat162_rn(x1.x*sc, x1.y*sc);
    bp[64+lane*2+1] = __floats2bfloat162_rn(x1.z*sc, x1.w*sc);
    if (lane == 0) g_lab8[row] = (unsigned char)lab[row];
}

// ---------------- Phase 2: symmetric fused GEMM -------------------------------
__device__ __forceinline__ void flush_rows(int slot, const int* myrow, int lane,
                                           float* accS, float* accP, int* accC) {
#pragma unroll
    for (int sl = 0; sl < 4; sl++) {
        float s = accS[sl], p = accP[sl], cc = (float)accC[sl];
        s  += __shfl_xor_sync(0xffffffffu, s, 1);  s  += __shfl_xor_sync(0xffffffffu, s, 2);
        p  += __shfl_xor_sync(0xffffffffu, p, 1);  p  += __shfl_xor_sync(0xffffffffu, p, 2);
        cc += __shfl_xor_sync(0xffffffffu, cc, 1); cc += __shfl_xor_sync(0xffffffffu, cc, 2);
        if ((lane & 3) == 0) {
            g_row[0][slot][myrow[sl]] = s;
            g_row[1][slot][myrow[sl]] = p;
            g_row[2][slot][myrow[sl]] = cc;
        }
        accS[sl] = 0.f; accP[sl] = 0.f; accC[sl] = 0;
    }
}

__global__ void __launch_bounds__(512, 1) gemm_fused_kernel() {
    extern __shared__ char smem[];
    const uint32_t sA_u = smem_u32(smem);
    const uint32_t sB_u = sA_u + SA_BYTES;
    float* sCol = (float*)(smem + SCOL_OFF);      // [3][4][128]

    const int tid  = threadIdx.x;
    const int warp = tid >> 5, lane = tid & 31;
    const int wm = warp >> 2, wn = warp & 3;      // 4 x 4
    const int g  = lane >> 2;
    const int q2 = (lane & 3) * 2;

    const int k  = blockIdx.x;                    // pair 0..31
    const int y  = blockIdx.y;                    // chunk 0..3
    const int t0 = y ? (16*y + 1) : 0;            // {0,17,33,49}
    const int cnt = y ? 16 : 17;
    const int nA = NBLK - k;                      // tiles in block k
    const int slot = y*4 + wn;

    const float invT = 1.0f/0.07f;
    const float K1 = invT * 1.44269504f;
    const float K2 = -10.0f * 1.44269504f;

    auto mapI = [&](int t) { return (t < nA) ? k : (NBLK-1) - k; };
    auto mapJ = [&](int t) { return (t < nA) ? k + t : ((NBLK-1)-k) + (t - nA); };

    int curI = mapI(t0);
    {
        const int colBase = mapJ(t0) * BN;
#pragma unroll
        for (int it = 0; it < 8; it++) {
            int idx = tid + it*THREADS;
            int r = idx >> 5, c = idx & 31;
            cpasync16(sB_u + r*512 + ((c ^ (r & 7)) << 4),
                      (const char*)(g_fn + (size_t)(colBase + r)*DDIM) + c*16);
        }
        CP_COMMIT();
    }
    {
        const int rowBase = curI * BM;
        for (int idx = tid; idx < BM*32; idx += THREADS) {
            int r = idx >> 5, c = idx & 31;
            uint4 val = ((const uint4*)(g_fn + (size_t)(rowBase + r)*DDIM))[c];
            *((uint4*)(smem + r*512 + ((c ^ (r & 7)) << 4))) = val;
        }
    }

    int myrow[4], mylab[4];
#pragma unroll
    for (int mt = 0; mt < 2; mt++)
#pragma unroll
        for (int h = 0; h < 2; h++) {
            int rl = wm*32 + mt*16 + h*8 + g;
            myrow[mt*2+h] = curI*BM + rl;
            mylab[mt*2+h] = g_lab8[curI*BM + rl];
        }

    float accS[4] = {0,0,0,0}, accP[4] = {0,0,0,0};
    int accC[4] = {0,0,0,0};

    for (int tt = 0; tt < cnt; tt++) {
        const int t = t0 + tt;
        const int I = mapI(t), J = mapJ(t);
        const int buf = tt & 1;
        const int colBase = J * BN;
        const uint32_t sBc = sB_u + buf*SB_BYTES;

        CP_WAIT0();
        __syncthreads();

        if (tt + 1 < cnt) {
            const int nb = mapJ(t + 1) * BN;
            const uint32_t sBn = sB_u + (buf^1)*SB_BYTES;
#pragma unroll
            for (int it = 0; it < 8; it++) {
                int idx = tid + it*THREADS;
                int r = idx >> 5, c = idx & 31;
                cpasync16(sBn + r*512 + ((c ^ (r & 7)) << 4),
                          (const char*)(g_fn + (size_t)(nb + r)*DDIM) + c*16);
            }
            CP_COMMIT();
        }

        if (I != curI) {
            flush_rows(slot, myrow, lane, accS, accP, accC);
            const int rowBase = I * BM;
            for (int idx = tid; idx < BM*32; idx += THREADS) {
                int r = idx >> 5, c = idx & 31;
                uint4 val = ((const uint4*)(g_fn + (size_t)(rowBase + r)*DDIM))[c];
                *((uint4*)(smem + r*512 + ((c ^ (r & 7)) << 4))) = val;
            }
#pragma unroll
            for (int mt = 0; mt < 2; mt++)
#pragma unroll
                for (int h = 0; h < 2; h++) {
                    int rl = wm*32 + mt*16 + h*8 + g;
                    myrow[mt*2+h] = rowBase + rl;
                    mylab[mt*2+h] = g_lab8[rowBase + rl];
                }
            curI = I;
            __syncthreads();
        }

        float c4[2][4][4];
#pragma unroll
        for (int mt = 0; mt < 2; mt++)
#pragma unroll
            for (int nt = 0; nt < 4; nt++)
#pragma unroll
                for (int e = 0; e < 4; e++) c4[mt][nt][e] = 0.f;

#pragma unroll
        for (int ks = 0; ks < DDIM/16; ks++) {
            uint32_t a[2][4], b[2][4];
            int kc = ks*2 + (lane >> 4);
#pragma unroll
            for (int mt = 0; mt < 2; mt++) {
                int row = wm*32 + mt*16 + (lane & 15);
                ldsm_x4(a[mt][0], a[mt][1], a[mt][2], a[mt][3],
                        sA_u + row*512 + ((kc ^ (row & 7)) << 4));
            }
#pragma unroll
            for (int bt = 0; bt < 2; bt++) {
                int nr = wn*32 + bt*16 + (lane & 15);
                ldsm_x4(b[bt][0], b[bt][1], b[bt][2], b[bt][3],
                        sBc + nr*512 + ((kc ^ (nr & 7)) << 4));
            }
#pragma unroll
            for (int mt = 0; mt < 2; mt++)
#pragma unroll
                for (int nt = 0; nt < 4; nt++) {
                    int bt = nt >> 1, lo = nt & 1;
                    mma16816(c4[mt][nt][0], c4[mt][nt][1], c4[mt][nt][2], c4[mt][nt][3],
                             a[mt][0], a[mt][1], a[mt][2], a[mt][3],
                             b[bt][lo], b[bt][2+lo]);
                }
        }

        if (I == J) {
#pragma unroll
            for (int nt = 0; nt < 4; nt++) {
                const int cl = wn*32 + nt*8 + q2;
                const int gj0 = colBase + cl;
                const int labj0 = __ldg(g_lab8 + gj0);
                const int labj1 = __ldg(g_lab8 + gj0 + 1);
#pragma unroll
                for (int mt = 0; mt < 2; mt++)
#pragma unroll
                    for (int h = 0; h < 2; h++) {
                        const int sl = mt*2 + h;
                        const int gi = myrow[sl];
#pragma unroll
                        for (int jj = 0; jj < 2; jj++) {
                            bool keep = (gi != gj0 + jj);
                            float dv = c4[mt][nt][h*2+jj];
                            float arg = fminf(fmaf(dv, K1, K2), 0.f);
                            if (keep) accS[sl] += ex2f(arg);
                            if (keep && ((jj ? labj1 : labj0) == mylab[sl])) {
                                accP[sl] = fmaf(dv, invT, accP[sl]);
                                accC[sl]++;
                            }
                        }
                    }
            }
        } else {
            float cS[4][2], cP[4][2]; int cC[4][2];
#pragma unroll
            for (int nt = 0; nt < 4; nt++) {
                cS[nt][0]=0.f; cS[nt][1]=0.f; cP[nt][0]=0.f; cP[nt][1]=0.f;
                cC[nt][0]=0;   cC[nt][1]=0;
            }
#pragma unroll
            for (int nt = 0; nt < 4; nt++) {
                const int cl = wn*32 + nt*8 + q2;
                const int gj0 = colBase + cl;
                const int labj0 = __ldg(g_lab8 + gj0);
                const int labj1 = __ldg(g_lab8 + gj0 + 1);
#pragma unroll
                for (int mt = 0; mt < 2; mt++)
#pragma unroll
                    for (int h = 0; h < 2; h++) {
                        const int sl = mt*2 + h;
#pragma unroll
                        for (int jj = 0; jj < 2; jj++) {
                            float dv = c4[mt][nt][h*2+jj];
                            float arg = fminf(fmaf(dv, K1, K2), 0.f);
                            float e = ex2f(arg);
                            accS[sl] += e;
                            cS[nt][jj] += e;
                            if ((jj ? labj1 : labj0) == mylab[sl]) {
                                accP[sl] = fmaf(dv, invT, accP[sl]);
                                accC[sl]++;
                                cP[nt][jj] += dv;
                                cC[nt][jj]++;
                            }
                        }
                    }
            }
#pragma unroll
            for (int nt = 0; nt < 4; nt++)
#pragma unroll
                for (int jj = 0; jj < 2; jj++) {
                    float vs = cS[nt][jj], vp = cP[nt][jj];
                    float vc = (float)cC[nt][jj];
                    vs += __shfl_xor_sync(0xffffffffu, vs, 4);
                    vs += __shfl_xor_sync(0xffffffffu, vs, 8);
                    vs += __shfl_xor_sync(0xffffffffu, vs, 16);
                    vp += __shfl_xor_sync(0xffffffffu, vp, 4);
                    vp += __shfl_xor_sync(0xffffffffu, vp, 8);
                    vp += __shfl_xor_sync(0xffffffffu, vp, 16);
                    vc += __shfl_xor_sync(0xffffffffu, vc, 4);
                    vc += __shfl_xor_sync(0xffffffffu, vc, 8);
                    vc += __shfl_xor_sync(0xffffffffu, vc, 16);
                    if (lane < 4) {
                        int col = wn*32 + nt*8 + lane*2 + jj;
                        sCol[0*512 + wm*128 + col] = vs;
                        sCol[1*512 + wm*128 + col] = vp;
                        sCol[2*512 + wm*128 + col] = vc;
                    }
                }
            __syncthreads();
            if (tid < 128) {
                const int cbi = 63*I - (I*(I-1))/2 + (J - I - 1);
                float a0 = sCol[tid]       + sCol[128+tid]  + sCol[256+tid]  + sCol[384+tid];
                float a1 = sCol[512+tid]   + sCol[640+tid]  + sCol[768+tid]  + sCol[896+tid];
                float a2 = sCol[1024+tid]  + sCol[1152+tid] + sCol[1280+tid] + sCol[1408+tid];
                g_colS[cbi*128 + tid] = a0;
                g_colP[cbi*128 + tid] = a1 * invT;
                g_colC[cbi*128 + tid] = a2;
            }
        }
    }

    flush_rows(slot, myrow, lane, accS, accP, accC);
}

// ---------------- Phase 3a: parallel triangular gather ------------------------
// grid (64, GCH), block 128: block (Jb, c) sums column partials for
// i in [c*8, c*8+8) ∩ [0, Jb). All loads independent (MLP=8). Every block
// writes (zeros when its range is empty) -> no pre-zeroing needed.
__global__ void gather_kernel() {
    const int tid = threadIdx.x;
    const int Jb  = blockIdx.x;
    const int c   = blockIdx.y;
    const int row = Jb*128 + tid;
    const int i0  = c*8;
    float s = 0.f, p = 0.f, cc = 0.f;
#pragma unroll
    for (int u = 0; u < 8; u++) {
        int i = i0 + u;
        if (i < Jb) {
            int idx = 63*i - (i*(i-1))/2 + (Jb - i - 1);
            s  += __ldg(g_colS + idx*128 + tid);
            p  += __ldg(g_colP + idx*128 + tid);
            cc += __ldg(g_colC + idx*128 + tid);
        }
    }
    g_gat[0][c][row] = s;
    g_gat[1][c][row] = p;
    g_gat[2][c][row] = cc;
}

// ---------------- Phase 3b: final loss (last-block-done) ----------------------
__global__ void reduce_kernel(float* __restrict__ out) {
    __shared__ float sL[128], sV[128];
    __shared__ unsigned int isLast;
    const int tid = threadIdx.x;
    const int row = blockIdx.x*128 + tid;

    float s = 0.f, p = 0.f, cc = 0.f;
#pragma unroll
    for (int b = 0; b < 16; b++) {
        s += g_row[0][b][row]; p += g_row[1][b][row]; cc += g_row[2][b][row];
    }
#pragma unroll
    for (int b = 0; b < GCH; b++) {
        s += g_gat[0][b][row]; p += g_gat[1][b][row]; cc += g_gat[2][b][row];
    }
    float l = 0.f, v = 0.f;
    if (cc > 0.f) { l = 10.f + logf(s) - p/cc; v = 1.f; }
    sL[tid] = l; sV[tid] = v; __syncthreads();
    for (int o = 64; o > 0; o >>= 1) {
        if (tid < o) { sL[tid] += sL[tid+o]; sV[tid] += sV[tid+o]; }
        __syncthreads();
    }
    if (tid == 0) {
        g_red[blockIdx.x][0] = sL[0]; g_red[blockIdx.x][1] = sV[0];
        __threadfence();
        isLast = (atomicAdd(&g_ctr, 1u) == 63u);
    }
    __syncthreads();
    if (isLast) {
        if (tid < 64) { sL[tid] = g_red[tid][0]; sV[tid] = g_red[tid][1]; }
        __syncthreads();
        for (int o = 32; o > 0; o >>= 1) {
            if (tid < o && tid + o < 64) { sL[tid] += sL[tid+o]; sV[tid] += sV[tid+o]; }
            __syncthreads();
        }
        if (tid == 0) {
            out[0] = (sV[0] > 0.f) ? sL[0]/sV[0] : 0.f;
            g_ctr = 0;          // reset for next graph replay
        }
    }
}

// ---------------- launch ------------------------------------------------------
extern "C" void kernel_launch(void* const* d_in, const int* in_sizes, int n_in,
                              void* d_out, int out_size) {
    const float*     feat = (const float*)d_in[0];
    const long long* lab  = (const long long*)d_in[1];

    zero_kernel<<<192, 512>>>();
    prep_kernel<<<NROWS/8, 256>>>(feat, lab);

    cudaFuncSetAttribute(gemm_fused_kernel,
                         cudaFuncAttributeMaxDynamicSharedMemorySize, SMEM_BYTES);
    dim3 grid(32, 4);
    gemm_fused_kernel<<<grid, THREADS, SMEM_BYTES>>>();

    gather_kernel<<<dim3(64, GCH), 128>>>();
    reduce_kernel<<<64, 128>>>((float*)d_out);
}

// round 13
// speedup vs baseline: 1.0123x; 1.0123x over previous
#include <cuda_runtime.h>
#include <cuda_bf16.h>
#include <cstdint>

#define NROWS 8192
#define DDIM  256
#define BM    128
#define BN    128
#define NBLK  64                      // 64 row blocks of 128
#define THREADS 512
#define NOFFD 2016                    // strict upper-triangle tiles

#define SA_BYTES (BM*512)             // 65536
#define SB_BYTES (BN*512)             // 65536 per buffer
#define SCOL_OFF (SA_BYTES + 2*SB_BYTES)         // 196608
#define SMEM_BYTES (SCOL_OFF + 3*4*128*4)        // +6144 = 202752

__device__ __align__(16) __nv_bfloat16 g_fn[NROWS*DDIM];
__device__ unsigned char g_lab8[NROWS];
__device__ float g_row[3][16][NROWS];            // [stat][slot y*4+wn][row]
__device__ float g_colS[NOFFD*128];
__device__ float g_colP[NOFFD*128];
__device__ float g_colC[NOFFD*128];
__device__ float g_red[64][2];
__device__ unsigned int g_ctr;

// ---------------- PTX helpers -------------------------------------------------
__device__ __forceinline__ uint32_t smem_u32(const void* p) {
    uint32_t a;
    asm("{ .reg .u64 t; cvta.to.shared.u64 t, %1; cvt.u32.u64 %0, t; }" : "=r"(a) : "l"(p));
    return a;
}
__device__ __forceinline__ float ex2f(float x) {
    float r; asm("ex2.approx.f32 %0, %1;" : "=f"(r) : "f"(x)); return r;
}
__device__ __forceinline__ void cpasync16(uint32_t dst, const void* src) {
    asm volatile("cp.async.cg.shared.global [%0], [%1], 16;" :: "r"(dst), "l"(src));
}
#define CP_COMMIT() asm volatile("cp.async.commit_group;" ::: "memory")
#define CP_WAIT0()  asm volatile("cp.async.wait_group 0;" ::: "memory")

__device__ __forceinline__ void ldsm_x4(uint32_t& r0, uint32_t& r1, uint32_t& r2,
                                        uint32_t& r3, uint32_t addr) {
    asm volatile("ldmatrix.sync.aligned.m8n8.x4.shared.b16 {%0,%1,%2,%3}, [%4];\n"
                 : "=r"(r0), "=r"(r1), "=r"(r2), "=r"(r3) : "r"(addr));
}
__device__ __forceinline__ void mma16816(float& d0, float& d1, float& d2, float& d3,
                                         uint32_t a0, uint32_t a1, uint32_t a2,
                                         uint32_t a3, uint32_t b0, uint32_t b1) {
    asm volatile("mma.sync.aligned.m16n8k16.row.col.f32.bf16.bf16.f32 "
                 "{%0,%1,%2,%3}, {%4,%5,%6,%7}, {%8,%9}, {%0,%1,%2,%3};\n"
                 : "+f"(d0), "+f"(d1), "+f"(d2), "+f"(d3)
                 : "r"(a0), "r"(a1), "r"(a2), "r"(a3), "r"(b0), "r"(b1));
}

// ---------------- Phase 1: normalize + quantize + zero row partials -----------
__global__ void prep_kernel(const float* __restrict__ feat,
                            const long long* __restrict__ lab) {
    const int gidx = blockIdx.x * blockDim.x + threadIdx.x;
    // fused zeroing of g_row: 3*16*8192 floats = 98304 float4
    if (gidx < 98304)
        ((float4*)&g_row[0][0][0])[gidx] = make_float4(0.f, 0.f, 0.f, 0.f);

    int row  = gidx >> 5;
    int lane = threadIdx.x & 31;
    if (row >= NROWS) return;
    const float4* fp = (const float4*)(feat + (size_t)row*DDIM);
    float4 x0 = fp[lane], x1 = fp[lane + 32];
    float ss = x0.x*x0.x + x0.y*x0.y + x0.z*x0.z + x0.w*x0.w
             + x1.x*x1.x + x1.y*x1.y + x1.z*x1.z + x1.w*x1.w;
#pragma unroll
    for (int o = 16; o > 0; o >>= 1) ss += __shfl_xor_sync(0xffffffffu, ss, o);
    float sc = 1.f / fmaxf(sqrtf(ss), 1e-6f);
    __nv_bfloat162* bp = (__nv_bfloat162*)(g_fn + (size_t)row*DDIM);
    bp[lane*2+0]    = __floats2bfloat162_rn(x0.x*sc, x0.y*sc);
    bp[lane*2+1]    = __floats2bfloat162_rn(x0.z*sc, x0.w*sc);
    bp[64+lane*2+0] = __floats2bfloat162_rn(x1.x*sc, x1.y*sc);
    bp[64+lane*2+1] = __floats2bfloat162_rn(x1.z*sc, x1.w*sc);
    if (lane == 0) g_lab8[row] = (unsigned char)lab[row];
}

// ---------------- Phase 2: symmetric fused GEMM -------------------------------
__device__ __forceinline__ void flush_rows(int slot, const int* myrow, int lane,
                                           float* accS, float* accP, int* accC) {
#pragma unroll
    for (int sl = 0; sl < 4; sl++) {
        float s = accS[sl], p = accP[sl], cc = (float)accC[sl];
        s  += __shfl_xor_sync(0xffffffffu, s, 1);  s  += __shfl_xor_sync(0xffffffffu, s, 2);
        p  += __shfl_xor_sync(0xffffffffu, p, 1);  p  += __shfl_xor_sync(0xffffffffu, p, 2);
        cc += __shfl_xor_sync(0xffffffffu, cc, 1); cc += __shfl_xor_sync(0xffffffffu, cc, 2);
        if ((lane & 3) == 0) {
            g_row[0][slot][myrow[sl]] = s;
            g_row[1][slot][myrow[sl]] = p;
            g_row[2][slot][myrow[sl]] = cc;
        }
        accS[sl] = 0.f; accP[sl] = 0.f; accC[sl] = 0;
    }
}

__global__ void __launch_bounds__(512, 1) gemm_fused_kernel() {
    extern __shared__ char smem[];
    const uint32_t sA_u = smem_u32(smem);
    const uint32_t sB_u = sA_u + SA_BYTES;
    float* sCol = (float*)(smem + SCOL_OFF);      // [3][4][128]

    const int tid  = threadIdx.x;
    const int warp = tid >> 5, lane = tid & 31;
    const int wm = warp >> 2, wn = warp & 3;      // 4 x 4
    const int g  = lane >> 2;
    const int q2 = (lane & 3) * 2;

    const int k  = blockIdx.x;                    // pair 0..31
    const int y  = blockIdx.y;                    // chunk 0..3
    const int t0 = y ? (16*y + 1) : 0;            // {0,17,33,49}
    const int cnt = y ? 16 : 17;
    const int nA = NBLK - k;                      // tiles in block k
    const int slot = y*4 + wn;

    const float invT = 1.0f/0.07f;
    const float K1 = invT * 1.44269504f;
    const float K2 = -10.0f * 1.44269504f;

    auto mapI = [&](int t) { return (t < nA) ? k : (NBLK-1) - k; };
    auto mapJ = [&](int t) { return (t < nA) ? k + t : ((NBLK-1)-k) + (t - nA); };

    int curI = mapI(t0);
    {
        const int colBase = mapJ(t0) * BN;
#pragma unroll
        for (int it = 0; it < 8; it++) {
            int idx = tid + it*THREADS;
            int r = idx >> 5, c = idx & 31;
            cpasync16(sB_u + r*512 + ((c ^ (r & 7)) << 4),
                      (const char*)(g_fn + (size_t)(colBase + r)*DDIM) + c*16);
        }
        CP_COMMIT();
    }
    {
        const int rowBase = curI * BM;
        for (int idx = tid; idx < BM*32; idx += THREADS) {
            int r = idx >> 5, c = idx & 31;
            uint4 val = ((const uint4*)(g_fn + (size_t)(rowBase + r)*DDIM))[c];
            *((uint4*)(smem + r*512 + ((c ^ (r & 7)) << 4))) = val;
        }
    }

    int myrow[4], mylab[4];
#pragma unroll
    for (int mt = 0; mt < 2; mt++)
#pragma unroll
        for (int h = 0; h < 2; h++) {
            int rl = wm*32 + mt*16 + h*8 + g;
            myrow[mt*2+h] = curI*BM + rl;
            mylab[mt*2+h] = g_lab8[curI*BM + rl];
        }

    float accS[4] = {0,0,0,0}, accP[4] = {0,0,0,0};
    int accC[4] = {0,0,0,0};

    for (int tt = 0; tt < cnt; tt++) {
        const int t = t0 + tt;
        const int I = mapI(t), J = mapJ(t);
        const int buf = tt & 1;
        const int colBase = J * BN;
        const uint32_t sBc = sB_u + buf*SB_BYTES;

        CP_WAIT0();
        __syncthreads();

        if (tt + 1 < cnt) {
            const int nb = mapJ(t + 1) * BN;
            const uint32_t sBn = sB_u + (buf^1)*SB_BYTES;
#pragma unroll
            for (int it = 0; it < 8; it++) {
                int idx = tid + it*THREADS;
                int r = idx >> 5, c = idx & 31;
                cpasync16(sBn + r*512 + ((c ^ (r & 7)) << 4),
                          (const char*)(g_fn + (size_t)(nb + r)*DDIM) + c*16);
            }
            CP_COMMIT();
        }

        if (I != curI) {
            flush_rows(slot, myrow, lane, accS, accP, accC);
            const int rowBase = I * BM;
            for (int idx = tid; idx < BM*32; idx += THREADS) {
                int r = idx >> 5, c = idx & 31;
                uint4 val = ((const uint4*)(g_fn + (size_t)(rowBase + r)*DDIM))[c];
                *((uint4*)(smem + r*512 + ((c ^ (r & 7)) << 4))) = val;
            }
#pragma unroll
            for (int mt = 0; mt < 2; mt++)
#pragma unroll
                for (int h = 0; h < 2; h++) {
                    int rl = wm*32 + mt*16 + h*8 + g;
                    myrow[mt*2+h] = rowBase + rl;
                    mylab[mt*2+h] = g_lab8[rowBase + rl];
                }
            curI = I;
            __syncthreads();
        }

        float c4[2][4][4];
#pragma unroll
        for (int mt = 0; mt < 2; mt++)
#pragma unroll
            for (int nt = 0; nt < 4; nt++)
#pragma unroll
                for (int e = 0; e < 4; e++) c4[mt][nt][e] = 0.f;

#pragma unroll
        for (int ks = 0; ks < DDIM/16; ks++) {
            uint32_t a[2][4], b[2][4];
            int kc = ks*2 + (lane >> 4);
#pragma unroll
            for (int mt = 0; mt < 2; mt++) {
                int row = wm*32 + mt*16 + (lane & 15);
                ldsm_x4(a[mt][0], a[mt][1], a[mt][2], a[mt][3],
                        sA_u + row*512 + ((kc ^ (row & 7)) << 4));
            }
#pragma unroll
            for (int bt = 0; bt < 2; bt++) {
                int nr = wn*32 + bt*16 + (lane & 15);
                ldsm_x4(b[bt][0], b[bt][1], b[bt][2], b[bt][3],
                        sBc + nr*512 + ((kc ^ (nr & 7)) << 4));
            }
#pragma unroll
            for (int mt = 0; mt < 2; mt++)
#pragma unroll
                for (int nt = 0; nt < 4; nt++) {
                    int bt = nt >> 1, lo = nt & 1;
                    mma16816(c4[mt][nt][0], c4[mt][nt][1], c4[mt][nt][2], c4[mt][nt][3],
                             a[mt][0], a[mt][1], a[mt][2], a[mt][3],
                             b[bt][lo], b[bt][2+lo]);
                }
        }

        if (I == J) {
#pragma unroll
            for (int nt = 0; nt < 4; nt++) {
                const int cl = wn*32 + nt*8 + q2;
                const int gj0 = colBase + cl;
                const int labj0 = __ldg(g_lab8 + gj0);
                const int labj1 = __ldg(g_lab8 + gj0 + 1);
#pragma unroll
                for (int mt = 0; mt < 2; mt++)
#pragma unroll
                    for (int h = 0; h < 2; h++) {
                        const int sl = mt*2 + h;
                        const int gi = myrow[sl];
#pragma unroll
                        for (int jj = 0; jj < 2; jj++) {
                            bool keep = (gi != gj0 + jj);
                            float dv = c4[mt][nt][h*2+jj];
                            float arg = fminf(fmaf(dv, K1, K2), 0.f);
                            if (keep) accS[sl] += ex2f(arg);
                            if (keep && ((jj ? labj1 : labj0) == mylab[sl])) {
                                accP[sl] = fmaf(dv, invT, accP[sl]);
                                accC[sl]++;
                            }
                        }
                    }
            }
        } else {
            float cS[4][2], cP[4][2]; int cC[4][2];
#pragma unroll
            for (int nt = 0; nt < 4; nt++) {
                cS[nt][0]=0.f; cS[nt][1]=0.f; cP[nt][0]=0.f; cP[nt][1]=0.f;
                cC[nt][0]=0;   cC[nt][1]=0;
            }
#pragma unroll
            for (int nt = 0; nt < 4; nt++) {
                const int cl = wn*32 + nt*8 + q2;
                const int gj0 = colBase + cl;
                const int labj0 = __ldg(g_lab8 + gj0);
                const int labj1 = __ldg(g_lab8 + gj0 + 1);
#pragma unroll
                for (int mt = 0; mt < 2; mt++)
#pragma unroll
                    for (int h = 0; h < 2; h++) {
                        const int sl = mt*2 + h;
#pragma unroll
                        for (int jj = 0; jj < 2; jj++) {
                            float dv = c4[mt][nt][h*2+jj];
                            float arg = fminf(fmaf(dv, K1, K2), 0.f);
                            float e = ex2f(arg);
                            accS[sl] += e;
                            cS[nt][jj] += e;
                            if ((jj ? labj1 : labj0) == mylab[sl]) {
                                accP[sl] = fmaf(dv, invT, accP[sl]);
                                accC[sl]++;
                                cP[nt][jj] += dv;
                                cC[nt][jj]++;
                            }
                        }
                    }
            }
#pragma unroll
            for (int nt = 0; nt < 4; nt++)
#pragma unroll
                for (int jj = 0; jj < 2; jj++) {
                    float vs = cS[nt][jj], vp = cP[nt][jj];
                    float vc = (float)cC[nt][jj];
                    vs += __shfl_xor_sync(0xffffffffu, vs, 4);
                    vs += __shfl_xor_sync(0xffffffffu, vs, 8);
                    vs += __shfl_xor_sync(0xffffffffu, vs, 16);
                    vp += __shfl_xor_sync(0xffffffffu, vp, 4);
                    vp += __shfl_xor_sync(0xffffffffu, vp, 8);
                    vp += __shfl_xor_sync(0xffffffffu, vp, 16);
                    vc += __shfl_xor_sync(0xffffffffu, vc, 4);
                    vc += __shfl_xor_sync(0xffffffffu, vc, 8);
                    vc += __shfl_xor_sync(0xffffffffu, vc, 16);
                    if (lane < 4) {
                        int col = wn*32 + nt*8 + lane*2 + jj;
                        sCol[0*512 + wm*128 + col] = vs;
                        sCol[1*512 + wm*128 + col] = vp;
                        sCol[2*512 + wm*128 + col] = vc;
                    }
                }
            __syncthreads();
            if (tid < 128) {
                const int cbi = 63*I - (I*(I-1))/2 + (J - I - 1);
                float a0 = sCol[tid]       + sCol[128+tid]  + sCol[256+tid]  + sCol[384+tid];
                float a1 = sCol[512+tid]   + sCol[640+tid]  + sCol[768+tid]  + sCol[896+tid];
                float a2 = sCol[1024+tid]  + sCol[1152+tid] + sCol[1280+tid] + sCol[1408+tid];
                g_colS[cbi*128 + tid] = a0;
                g_colP[cbi*128 + tid] = a1 * invT;
                g_colC[cbi*128 + tid] = a2;
            }
        }
    }

    flush_rows(slot, myrow, lane, accS, accP, accC);
}

// ---------------- Phase 3: fused gather + loss (last-block-done) --------------
// grid 64, block 512. Thread = (row r = tid&127, chunk c = tid>>7).
// Chunk c: row-slots [4c,4c+4) + column partials i in [16c,16c+16) ∩ [0,Jb).
__global__ void __launch_bounds__(512, 1) reduce_kernel(float* __restrict__ out) {
    __shared__ float sS[4][128], sP[4][128], sC[4][128];
    __shared__ float sL[128], sV[128];
    __shared__ unsigned int isLast;
    const int tid = threadIdx.x;
    const int r   = tid & 127, c = tid >> 7;
    const int Jb  = blockIdx.x;
    const int row = Jb*128 + r;

    float s = 0.f, p = 0.f, cc = 0.f;
#pragma unroll
    for (int u = 0; u < 4; u++) {
        int b = c*4 + u;
        s += g_row[0][b][row]; p += g_row[1][b][row]; cc += g_row[2][b][row];
    }
#pragma unroll
    for (int u = 0; u < 16; u++) {
        int i = c*16 + u;
        if (i < Jb) {
            int idx = 63*i - (i*(i-1))/2 + (Jb - i - 1);
            s  += __ldg(g_colS + idx*128 + r);
            p  += __ldg(g_colP + idx*128 + r);
            cc += __ldg(g_colC + idx*128 + r);
        }
    }
    sS[c][r] = s; sP[c][r] = p; sC[c][r] = cc;
    __syncthreads();
    if (tid < 128) {
        s  = sS[0][r] + sS[1][r] + sS[2][r] + sS[3][r];
        p  = sP[0][r] + sP[1][r] + sP[2][r] + sP[3][r];
        cc = sC[0][r] + sC[1][r] + sC[2][r] + sC[3][r];
        float l = 0.f, v = 0.f;
        if (cc > 0.f) { l = 10.f + logf(s) - p/cc; v = 1.f; }
        sL[r] = l; sV[r] = v;
    }
    __syncthreads();
    for (int o = 64; o > 0; o >>= 1) {
        if (tid < o) { sL[tid] += sL[tid+o]; sV[tid] += sV[tid+o]; }
        __syncthreads();
    }
    if (tid == 0) {
        g_red[blockIdx.x][0] = sL[0]; g_red[blockIdx.x][1] = sV[0];
        __threadfence();
        isLast = (atomicAdd(&g_ctr, 1u) == 63u);
    }
    __syncthreads();
    if (isLast) {
        if (tid < 64) { sL[tid] = g_red[tid][0]; sV[tid] = g_red[tid][1]; }
        __syncthreads();
        for (int o = 32; o > 0; o >>= 1) {
            if (tid < o && tid + o < 64) { sL[tid] += sL[tid+o]; sV[tid] += sV[tid+o]; }
            __syncthreads();
        }
        if (tid == 0) {
            out[0] = (sV[0] > 0.f) ? sL[0]/sV[0] : 0.f;
            g_ctr = 0;          // reset for next graph replay
        }
    }
}

// ---------------- launch ------------------------------------------------------
extern "C" void kernel_launch(void* const* d_in, const int* in_sizes, int n_in,
                              void* d_out, int out_size) {
    const float*     feat = (const float*)d_in[0];
    const long long* lab  = (const long long*)d_in[1];

    prep_kernel<<<NROWS/8, 256>>>(feat, lab);

    cudaFuncSetAttribute(gemm_fused_kernel,
                         cudaFuncAttributeMaxDynamicSharedMemorySize, SMEM_BYTES);
    dim3 grid(32, 4);
    gemm_fused_kernel<<<grid, THREADS, SMEM_BYTES>>>();

    reduce_kernel<<<64, 512>>>((float*)d_out);
}

// round 14
// speedup vs baseline: 1.1168x; 1.1032x over previous
#include <cuda_runtime.h>
#include <cuda_bf16.h>
#include <cstdint>

#define NROWS 8192
#define DDIM  256
#define BM    128
#define BN    128
#define NBLK  64                      // 64 row blocks of 128
#define THREADS 512
#define NOFFD 2016                    // strict upper-triangle tiles
#define NTOT  2080                    // total tiles (upper triangle incl diag)
#define NCTA  148
#define NSLOT 32                      // row-partial slots: (cta&7)*4 + wn

#define SA_BYTES (BM*512)             // 65536
#define SB_BYTES (BN*512)             // 65536 per buffer
#define SCOL_OFF (SA_BYTES + 2*SB_BYTES)         // 196608
#define SMEM_BYTES (SCOL_OFF + 3*4*128*4)        // +6144 = 202752

__device__ __align__(16) __nv_bfloat16 g_fn[NROWS*DDIM];
__device__ unsigned char g_lab8[NROWS];
__device__ float g_row[3][NSLOT][NROWS];         // [stat][slot][row]
__device__ float g_colS[NOFFD*128];
__device__ float g_colP[NOFFD*128];
__device__ float g_colC[NOFFD*128];
__device__ float g_red[64][2];
__device__ unsigned int g_ctr;

// ---------------- PTX helpers -------------------------------------------------
__device__ __forceinline__ uint32_t smem_u32(const void* p) {
    uint32_t a;
    asm("{ .reg .u64 t; cvta.to.shared.u64 t, %1; cvt.u32.u64 %0, t; }" : "=r"(a) : "l"(p));
    return a;
}
__device__ __forceinline__ float ex2f(float x) {
    float r; asm("ex2.approx.f32 %0, %1;" : "=f"(r) : "f"(x)); return r;
}
__device__ __forceinline__ void cpasync16(uint32_t dst, const void* src) {
    asm volatile("cp.async.cg.shared.global [%0], [%1], 16;" :: "r"(dst), "l"(src));
}
#define CP_COMMIT() asm volatile("cp.async.commit_group;" ::: "memory")
#define CP_WAIT0()  asm volatile("cp.async.wait_group 0;" ::: "memory")

__device__ __forceinline__ void ldsm_x4(uint32_t& r0, uint32_t& r1, uint32_t& r2,
                                        uint32_t& r3, uint32_t addr) {
    asm volatile("ldmatrix.sync.aligned.m8n8.x4.shared.b16 {%0,%1,%2,%3}, [%4];\n"
                 : "=r"(r0), "=r"(r1), "=r"(r2), "=r"(r3) : "r"(addr));
}
__device__ __forceinline__ void mma16816(float& d0, float& d1, float& d2, float& d3,
                                         uint32_t a0, uint32_t a1, uint32_t a2,
                                         uint32_t a3, uint32_t b0, uint32_t b1) {
    asm volatile("mma.sync.aligned.m16n8k16.row.col.f32.bf16.bf16.f32 "
                 "{%0,%1,%2,%3}, {%4,%5,%6,%7}, {%8,%9}, {%0,%1,%2,%3};\n"
                 : "+f"(d0), "+f"(d1), "+f"(d2), "+f"(d3)
                 : "r"(a0), "r"(a1), "r"(a2), "r"(a3), "r"(b0), "r"(b1));
}

// tile id g (0..2079) -> (I, J) via pair ordering
__device__ __forceinline__ void map_tile(int gidx, int& I, int& J) {
    int k = gidx / 65, t = gidx - k*65;
    int nA = NBLK - k;
    if (t < nA) { I = k; J = k + t; }
    else        { I = (NBLK-1) - k; J = I + (t - nA); }
}

// ---------------- Phase 1: normalize + quantize + zero row partials -----------
__global__ void prep_kernel(const float* __restrict__ feat,
                            const long long* __restrict__ lab) {
    const int gidx = blockIdx.x * blockDim.x + threadIdx.x;
    // fused zeroing of g_row: 3*32*8192 floats = 196608 float4 (262144 threads)
    if (gidx < 196608)
        ((float4*)&g_row[0][0][0])[gidx] = make_float4(0.f, 0.f, 0.f, 0.f);

    int row  = gidx >> 5;
    int lane = threadIdx.x & 31;
    if (row >= NROWS) return;
    const float4* fp = (const float4*)(feat + (size_t)row*DDIM);
    float4 x0 = fp[lane], x1 = fp[lane + 32];
    float ss = x0.x*x0.x + x0.y*x0.y + x0.z*x0.z + x0.w*x0.w
             + x1.x*x1.x + x1.y*x1.y + x1.z*x1.z + x1.w*x1.w;
#pragma unroll
    for (int o = 16; o > 0; o >>= 1) ss += __shfl_xor_sync(0xffffffffu, ss, o);
    float sc = 1.f / fmaxf(sqrtf(ss), 1e-6f);
    __nv_bfloat162* bp = (__nv_bfloat162*)(g_fn + (size_t)row*DDIM);
    bp[lane*2+0]    = __floats2bfloat162_rn(x0.x*sc, x0.y*sc);
    bp[lane*2+1]    = __floats2bfloat162_rn(x0.z*sc, x0.w*sc);
    bp[64+lane*2+0] = __floats2bfloat162_rn(x1.x*sc, x1.y*sc);
    bp[64+lane*2+1] = __floats2bfloat162_rn(x1.z*sc, x1.w*sc);
    if (lane == 0) g_lab8[row] = (unsigned char)lab[row];
}

// ---------------- Phase 2: symmetric fused GEMM (148-CTA balanced) ------------
__device__ __forceinline__ void flush_rows(int slot, const int* myrow, int lane,
                                           float* accS, float* accP, int* accC) {
#pragma unroll
    for (int sl = 0; sl < 4; sl++) {
        float s = accS[sl], p = accP[sl], cc = (float)accC[sl];
        s  += __shfl_xor_sync(0xffffffffu, s, 1);  s  += __shfl_xor_sync(0xffffffffu, s, 2);
        p  += __shfl_xor_sync(0xffffffffu, p, 1);  p  += __shfl_xor_sync(0xffffffffu, p, 2);
        cc += __shfl_xor_sync(0xffffffffu, cc, 1); cc += __shfl_xor_sync(0xffffffffu, cc, 2);
        if ((lane & 3) == 0) {
            g_row[0][slot][myrow[sl]] = s;
            g_row[1][slot][myrow[sl]] = p;
            g_row[2][slot][myrow[sl]] = cc;
        }
        accS[sl] = 0.f; accP[sl] = 0.f; accC[sl] = 0;
    }
}

__global__ void __launch_bounds__(512, 1) gemm_fused_kernel() {
    extern __shared__ char smem[];
    const uint32_t sA_u = smem_u32(smem);
    const uint32_t sB_u = sA_u + SA_BYTES;
    float* sCol = (float*)(smem + SCOL_OFF);      // [3][4][128]

    const int tid  = threadIdx.x;
    const int warp = tid >> 5, lane = tid & 31;
    const int wm = warp >> 2, wn = warp & 3;      // 4 x 4
    const int g  = lane >> 2;
    const int q2 = (lane & 3) * 2;

    const int cta  = blockIdx.x;
    const int gBeg = (cta * NTOT) / NCTA;
    const int gEnd = ((cta + 1) * NTOT) / NCTA;
    const int slot = ((cta & 7) << 2) | wn;       // collision-free: <=6 consecutive
                                                  // CTAs share a row block

    const float invT = 1.0f/0.07f;
    const float K1 = invT * 1.44269504f;
    const float K2 = -10.0f * 1.44269504f;

    // prolog: prefetch B for first tile, load A for its I
    int curI, J0;
    map_tile(gBeg, curI, J0);
    {
        const int colBase = J0 * BN;
#pragma unroll
        for (int it = 0; it < 8; it++) {
            int idx = tid + it*THREADS;
            int r = idx >> 5, c = idx & 31;
            cpasync16(sB_u + r*512 + ((c ^ (r & 7)) << 4),
                      (const char*)(g_fn + (size_t)(colBase + r)*DDIM) + c*16);
        }
        CP_COMMIT();
    }
    {
        const int rowBase = curI * BM;
        for (int idx = tid; idx < BM*32; idx += THREADS) {
            int r = idx >> 5, c = idx & 31;
            uint4 val = ((const uint4*)(g_fn + (size_t)(rowBase + r)*DDIM))[c];
            *((uint4*)(smem + r*512 + ((c ^ (r & 7)) << 4))) = val;
        }
    }

    int myrow[4], mylab[4];
#pragma unroll
    for (int mt = 0; mt < 2; mt++)
#pragma unroll
        for (int h = 0; h < 2; h++) {
            int rl = wm*32 + mt*16 + h*8 + g;
            myrow[mt*2+h] = curI*BM + rl;
            mylab[mt*2+h] = g_lab8[curI*BM + rl];
        }

    float accS[4] = {0,0,0,0}, accP[4] = {0,0,0,0};
    int accC[4] = {0,0,0,0};

    for (int t = gBeg; t < gEnd; t++) {
        int I, J;
        map_tile(t, I, J);
        const int buf = (t - gBeg) & 1;
        const int colBase = J * BN;
        const uint32_t sBc = sB_u + buf*SB_BYTES;

        CP_WAIT0();
        __syncthreads();

        if (t + 1 < gEnd) {
            int In, Jn;
            map_tile(t + 1, In, Jn);
            const int nb = Jn * BN;
            const uint32_t sBn = sB_u + (buf^1)*SB_BYTES;
#pragma unroll
            for (int it = 0; it < 8; it++) {
                int idx = tid + it*THREADS;
                int r = idx >> 5, c = idx & 31;
                cpasync16(sBn + r*512 + ((c ^ (r & 7)) << 4),
                          (const char*)(g_fn + (size_t)(nb + r)*DDIM) + c*16);
            }
            CP_COMMIT();
        }

        if (I != curI) {
            flush_rows(slot, myrow, lane, accS, accP, accC);
            const int rowBase = I * BM;
            for (int idx = tid; idx < BM*32; idx += THREADS) {
                int r = idx >> 5, c = idx & 31;
                uint4 val = ((const uint4*)(g_fn + (size_t)(rowBase + r)*DDIM))[c];
                *((uint4*)(smem + r*512 + ((c ^ (r & 7)) << 4))) = val;
            }
#pragma unroll
            for (int mt = 0; mt < 2; mt++)
#pragma unroll
                for (int h = 0; h < 2; h++) {
                    int rl = wm*32 + mt*16 + h*8 + g;
                    myrow[mt*2+h] = rowBase + rl;
                    mylab[mt*2+h] = g_lab8[rowBase + rl];
                }
            curI = I;
            __syncthreads();
        }

        float c4[2][4][4];
#pragma unroll
        for (int mt = 0; mt < 2; mt++)
#pragma unroll
            for (int nt = 0; nt < 4; nt++)
#pragma unroll
                for (int e = 0; e < 4; e++) c4[mt][nt][e] = 0.f;

#pragma unroll
        for (int ks = 0; ks < DDIM/16; ks++) {
            uint32_t a[2][4], b[2][4];
            int kc = ks*2 + (lane >> 4);
#pragma unroll
            for (int mt = 0; mt < 2; mt++) {
                int row = wm*32 + mt*16 + (lane & 15);
                ldsm_x4(a[mt][0], a[mt][1], a[mt][2], a[mt][3],
                        sA_u + row*512 + ((kc ^ (row & 7)) << 4));
            }
#pragma unroll
            for (int bt = 0; bt < 2; bt++) {
                int nr = wn*32 + bt*16 + (lane & 15);
                ldsm_x4(b[bt][0], b[bt][1], b[bt][2], b[bt][3],
                        sBc + nr*512 + ((kc ^ (nr & 7)) << 4));
            }
#pragma unroll
            for (int mt = 0; mt < 2; mt++)
#pragma unroll
                for (int nt = 0; nt < 4; nt++) {
                    int bt = nt >> 1, lo = nt & 1;
                    mma16816(c4[mt][nt][0], c4[mt][nt][1], c4[mt][nt][2], c4[mt][nt][3],
                             a[mt][0], a[mt][1], a[mt][2], a[mt][3],
                             b[bt][lo], b[bt][2+lo]);
                }
        }

        if (I == J) {
#pragma unroll
            for (int nt = 0; nt < 4; nt++) {
                const int cl = wn*32 + nt*8 + q2;
                const int gj0 = colBase + cl;
                const int labj0 = __ldg(g_lab8 + gj0);
                const int labj1 = __ldg(g_lab8 + gj0 + 1);
#pragma unroll
                for (int mt = 0; mt < 2; mt++)
#pragma unroll
                    for (int h = 0; h < 2; h++) {
                        const int sl = mt*2 + h;
                        const int gi = myrow[sl];
#pragma unroll
                        for (int jj = 0; jj < 2; jj++) {
                            bool keep = (gi != gj0 + jj);
                            float dv = c4[mt][nt][h*2+jj];
                            float arg = fminf(fmaf(dv, K1, K2), 0.f);
                            if (keep) accS[sl] += ex2f(arg);
                            if (keep && ((jj ? labj1 : labj0) == mylab[sl])) {
                                accP[sl] = fmaf(dv, invT, accP[sl]);
                                accC[sl]++;
                            }
                        }
                    }
            }
        } else {
            float cS[4][2], cP[4][2]; int cC[4][2];
#pragma unroll
            for (int nt = 0; nt < 4; nt++) {
                cS[nt][0]=0.f; cS[nt][1]=0.f; cP[nt][0]=0.f; cP[nt][1]=0.f;
                cC[nt][0]=0;   cC[nt][1]=0;
            }
#pragma unroll
            for (int nt = 0; nt < 4; nt++) {
                const int cl = wn*32 + nt*8 + q2;
                const int gj0 = colBase + cl;
                const int labj0 = __ldg(g_lab8 + gj0);
                const int labj1 = __ldg(g_lab8 + gj0 + 1);
#pragma unroll
                for (int mt = 0; mt < 2; mt++)
#pragma unroll
                    for (int h = 0; h < 2; h++) {
                        const int sl = mt*2 + h;
#pragma unroll
                        for (int jj = 0; jj < 2; jj++) {
                            float dv = c4[mt][nt][h*2+jj];
                            float arg = fminf(fmaf(dv, K1, K2), 0.f);
                            float e = ex2f(arg);
                            accS[sl] += e;
                            cS[nt][jj] += e;
                            if ((jj ? labj1 : labj0) == mylab[sl]) {
                                accP[sl] = fmaf(dv, invT, accP[sl]);
                                accC[sl]++;
                                cP[nt][jj] += dv;
                                cC[nt][jj]++;
                            }
                        }
                    }
            }
#pragma unroll
            for (int nt = 0; nt < 4; nt++)
#pragma unroll
                for (int jj = 0; jj < 2; jj++) {
                    float vs = cS[nt][jj], vp = cP[nt][jj];
                    float vc = (float)cC[nt][jj];
                    vs += __shfl_xor_sync(0xffffffffu, vs, 4);
                    vs += __shfl_xor_sync(0xffffffffu, vs, 8);
                    vs += __shfl_xor_sync(0xffffffffu, vs, 16);
                    vp += __shfl_xor_sync(0xffffffffu, vp, 4);
                    vp += __shfl_xor_sync(0xffffffffu, vp, 8);
                    vp += __shfl_xor_sync(0xffffffffu, vp, 16);
                    vc += __shfl_xor_sync(0xffffffffu, vc, 4);
                    vc += __shfl_xor_sync(0xffffffffu, vc, 8);
                    vc += __shfl_xor_sync(0xffffffffu, vc, 16);
                    if (lane < 4) {
                        int col = wn*32 + nt*8 + lane*2 + jj;
                        sCol[0*512 + wm*128 + col] = vs;
                        sCol[1*512 + wm*128 + col] = vp;
                        sCol[2*512 + wm*128 + col] = vc;
                    }
                }
            __syncthreads();
            if (tid < 128) {
                const int cbi = 63*I - (I*(I-1))/2 + (J - I - 1);
                float a0 = sCol[tid]       + sCol[128+tid]  + sCol[256+tid]  + sCol[384+tid];
                float a1 = sCol[512+tid]   + sCol[640+tid]  + sCol[768+tid]  + sCol[896+tid];
                float a2 = sCol[1024+tid]  + sCol[1152+tid] + sCol[1280+tid] + sCol[1408+tid];
                g_colS[cbi*128 + tid] = a0;
                g_colP[cbi*128 + tid] = a1 * invT;
                g_colC[cbi*128 + tid] = a2;
            }
        }
    }

    flush_rows(slot, myrow, lane, accS, accP, accC);
}

// ---------------- Phase 3: fused gather + loss (last-block-done) --------------
// grid 64, block 512. Thread = (row r = tid&127, chunk c = tid>>7).
// Chunk c: row slots [8c,8c+8) + column partials i in [16c,16c+16) ∩ [0,Jb).
__global__ void __launch_bounds__(512, 1) reduce_kernel(float* __restrict__ out) {
    __shared__ float sS[4][128], sP[4][128], sC[4][128];
    __shared__ float sL[128], sV[128];
    __shared__ unsigned int isLast;
    const int tid = threadIdx.x;
    const int r   = tid & 127, c = tid >> 7;
    const int Jb  = blockIdx.x;
    const int row = Jb*128 + r;

    float s = 0.f, p = 0.f, cc = 0.f;
#pragma unroll
    for (int u = 0; u < 8; u++) {
        int b = c*8 + u;
        s += g_row[0][b][row]; p += g_row[1][b][row]; cc += g_row[2][b][row];
    }
#pragma unroll
    for (int u = 0; u < 16; u++) {
        int i = c*16 + u;
        if (i < Jb) {
            int idx = 63*i - (i*(i-1))/2 + (Jb - i - 1);
            s  += __ldg(g_colS + idx*128 + r);
            p  += __ldg(g_colP + idx*128 + r);
            cc += __ldg(g_colC + idx*128 + r);
        }
    }
    sS[c][r] = s; sP[c][r] = p; sC[c][r] = cc;
    __syncthreads();
    if (tid < 128) {
        s  = sS[0][r] + sS[1][r] + sS[2][r] + sS[3][r];
        p  = sP[0][r] + sP[1][r] + sP[2][r] + sP[3][r];
        cc = sC[0][r] + sC[1][r] + sC[2][r] + sC[3][r];
        float l = 0.f, v = 0.f;
        if (cc > 0.f) { l = 10.f + logf(s) - p/cc; v = 1.f; }
        sL[r] = l; sV[r] = v;
    }
    __syncthreads();
    for (int o = 64; o > 0; o >>= 1) {
        if (tid < o) { sL[tid] += sL[tid+o]; sV[tid] += sV[tid+o]; }
        __syncthreads();
    }
    if (tid == 0) {
        g_red[blockIdx.x][0] = sL[0]; g_red[blockIdx.x][1] = sV[0];
        __threadfence();
        isLast = (atomicAdd(&g_ctr, 1u) == 63u);
    }
    __syncthreads();
    if (isLast) {
        if (tid < 64) { sL[tid] = g_red[tid][0]; sV[tid] = g_red[tid][1]; }
        __syncthreads();
        for (int o = 32; o > 0; o >>= 1) {
            if (tid < o && tid + o < 64) { sL[tid] += sL[tid+o]; sV[tid] += sV[tid+o]; }
            __syncthreads();
        }
        if (tid == 0) {
            out[0] = (sV[0] > 0.f) ? sL[0]/sV[0] : 0.f;
            g_ctr = 0;          // reset for next graph replay
        }
    }
}

// ---------------- launch ------------------------------------------------------
extern "C" void kernel_launch(void* const* d_in, const int* in_sizes, int n_in,
                              void* d_out, int out_size) {
    const float*     feat = (const float*)d_in[0];
    const long long* lab  = (const long long*)d_in[1];

    prep_kernel<<<NROWS/8, 256>>>(feat, lab);

    cudaFuncSetAttribute(gemm_fused_kernel,
                         cudaFuncAttributeMaxDynamicSharedMemorySize, SMEM_BYTES);
    gemm_fused_kernel<<<NCTA, THREADS, SMEM_BYTES>>>();

    reduce_kernel<<<64, 512>>>((float*)d_out);
}